// round 15
// baseline (speedup 1.0000x reference)
#include <cuda_runtime.h>
#include <cuda_bf16.h>
#include <cstdint>

// ---------------------------------------------------------------------------
// Problem constants
// ---------------------------------------------------------------------------
#define B_    8
#define LQ_   2048
#define LKV_  2048
#define DQ_   512
#define DC_   768
#define ATT_SCALE 0.044194173824159216f   // 1/sqrt(512)

// ---------------------------------------------------------------------------
// Scratch (device globals — runtime allocation is forbidden). bf16 planes.
// ---------------------------------------------------------------------------
__device__ __align__(256) __nv_bfloat16 g_Qh  [(size_t)B_ * LQ_  * DQ_];
__device__ __align__(256) __nv_bfloat16 g_Ql  [(size_t)B_ * LQ_  * DQ_];
__device__ __align__(256) __nv_bfloat16 g_keyh[(size_t)B_ * LKV_ * DC_];
__device__ __align__(256) __nv_bfloat16 g_keyl[(size_t)B_ * LKV_ * DC_];
__device__ __align__(256) __nv_bfloat16 g_valh[(size_t)B_ * LKV_ * DC_];
__device__ __align__(256) __nv_bfloat16 g_vall[(size_t)B_ * LKV_ * DC_];
__device__ __align__(256) __nv_bfloat16 g_Kph [(size_t)B_ * LKV_ * DQ_];   // key@Wk+bk (pair)
__device__ __align__(256) __nv_bfloat16 g_Kpl [(size_t)B_ * LKV_ * DQ_];
__device__ __align__(256) __nv_bfloat16 g_VpTh[(size_t)B_ * DQ_ * LKV_];   // (value@Wvo)^T (pair)
__device__ __align__(256) __nv_bfloat16 g_VpTl[(size_t)B_ * DQ_ * LKV_];
__device__ __align__(256) __nv_bfloat16 g_Eh  [(size_t)B_ * LQ_ * LKV_];   // exp(scale*QKp^T) (pair)
__device__ __align__(256) __nv_bfloat16 g_El  [(size_t)B_ * LQ_ * LKV_];
__device__ __align__(256) __nv_bfloat16 g_WkTh[(size_t)DQ_ * DC_];
__device__ __align__(256) __nv_bfloat16 g_WkTl[(size_t)DQ_ * DC_];
__device__ __align__(256) __nv_bfloat16 g_WoTh[(size_t)DQ_ * DQ_];
__device__ __align__(256) __nv_bfloat16 g_WoTl[(size_t)DQ_ * DQ_];
__device__ __align__(256) __nv_bfloat16 g_Wvh [(size_t)DC_ * DQ_];
__device__ __align__(256) __nv_bfloat16 g_Wvl [(size_t)DC_ * DQ_];
__device__ __align__(256) __nv_bfloat16 g_WvoTh[(size_t)DQ_ * DC_];        // (Wv@Wo)^T (pair)
__device__ __align__(256) __nv_bfloat16 g_WvoTl[(size_t)DQ_ * DC_];
__device__ __align__(256) float g_R  [(size_t)B_ * LQ_];                   // recip row sums
__device__ __align__(256) float g_bo2[DQ_];                                // bv@Wo + bo

// ---------------------------------------------------------------------------
// PTX helpers — baseline sm_103 ISA only (NO tcgen05, NO cp.async)
// ---------------------------------------------------------------------------
__device__ __forceinline__ uint32_t smem_u32(const void* p) {
    uint32_t a;
    asm("{ .reg .u64 t; cvta.to.shared.u64 t, %1; cvt.u32.u64 %0, t; }"
        : "=r"(a) : "l"(p));
    return a;
}
// ldmatrix x4: four 8x8 b16 tiles
__device__ __forceinline__ void ldsm4(uint32_t* r, uint32_t addr) {
    asm volatile("ldmatrix.sync.aligned.m8n8.x4.shared.b16 {%0,%1,%2,%3}, [%4];"
        : "=r"(r[0]), "=r"(r[1]), "=r"(r[2]), "=r"(r[3]) : "r"(addr));
}
// mma m16n8k16 bf16 -> f32 accumulate
__device__ __forceinline__ void hmma(float* d, const uint32_t* a, const uint32_t* b) {
    asm volatile(
        "mma.sync.aligned.m16n8k16.row.col.f32.bf16.bf16.f32 "
        "{%0,%1,%2,%3}, {%4,%5,%6,%7}, {%8,%9}, {%0,%1,%2,%3};"
        : "+f"(d[0]), "+f"(d[1]), "+f"(d[2]), "+f"(d[3])
        : "r"(a[0]), "r"(a[1]), "r"(a[2]), "r"(a[3]), "r"(b[0]), "r"(b[1]));
}
// Pack two fp32 into bf16x2. Result low half = first arg.
__device__ __forceinline__ uint32_t pk2(float lo, float hi) {
    uint32_t r;
    asm("cvt.rn.bf16x2.f32 %0, %1, %2;" : "=r"(r) : "f"(hi), "f"(lo));
    return r;
}
// Split float4 into bf16-hi quad + bf16-lo (residual) quad
__device__ __forceinline__ void split4(float4 v, uint2& h, uint2& l) {
    uint32_t h01 = pk2(v.x, v.y);
    uint32_t h23 = pk2(v.z, v.w);
    float f0 = __uint_as_float(h01 << 16);
    float f1 = __uint_as_float(h01 & 0xffff0000u);
    float f2 = __uint_as_float(h23 << 16);
    float f3 = __uint_as_float(h23 & 0xffff0000u);
    h = make_uint2(h01, h23);
    l = make_uint2(pk2(v.x - f0, v.y - f1), pk2(v.z - f2, v.w - f3));
}

// ---------------------------------------------------------------------------
// Tensor-core NT GEMM on pre-split bf16 planes (R14-proven machinery):
//   C[m,n] = epi( sum_k A[m,k]*B[n,k] )  A:[M,K] B:[N,K] bf16, k-contiguous
// TERMS==3: a=Ah+Al, b=Bh+Bl, 3 MMAs (ah*bh+ah*bl+al*bh) -> fp32-class
// TERMS==1: plain bf16, 1 MMA
// OMODE: 0 = bf16 hi+lo pair out; 1 = bf16 hi out; 2 = fp32 rowscale*v+bias out
// CTA tile 128x128, k-chunk 32, single static smem buffer + register prefetch.
// 8 warps, 64x32 warp tiles. 80B smem pitch -> conflict-free ldmatrix.
// ---------------------------------------------------------------------------
template <int TERMS, int DO_EXP, int OMODE>
__global__ __launch_bounds__(256, 2)
void bgemm(const __nv_bfloat16* __restrict__ Ah, const __nv_bfloat16* __restrict__ Al,
           const __nv_bfloat16* __restrict__ Bh, const __nv_bfloat16* __restrict__ Bl,
           void* __restrict__ O1, void* __restrict__ O2,
           int M, int N, int K, long bsA, long bsB, long bsC,
           const float* __restrict__ bias, const float* __restrict__ rowscale,
           float alpha)
{
    constexpr int PLB    = 10240;                    // 128 rows * 80B pitch
    constexpr int OFF_AH = 0;
    constexpr int OFF_AL = PLB;                      // TERMS==3 only
    constexpr int OFF_BH = (TERMS == 3) ? 2 * PLB : PLB;
    constexpr int OFF_BL = 3 * PLB;                  // TERMS==3 only

    __shared__ __align__(128) char sm[(TERMS == 3) ? 4 * PLB : 2 * PLB];
    const uint32_t sb = smem_u32(sm);

    const int tid  = threadIdx.x;
    const int warp = tid >> 5, ln = tid & 31;
    const int z    = blockIdx.z;
    const int n0   = blockIdx.x * 128;
    const int m0   = blockIdx.y * 128;

    Ah += (long)z * bsA + (long)m0 * K;
    Bh += (long)z * bsB + (long)n0 * K;
    if (TERMS == 3) { Al += (long)z * bsA + (long)m0 * K;
                      Bl += (long)z * bsB + (long)n0 * K; }

    const int mb = (warp >> 2) * 64;
    const int nb = (warp & 3) * 32;

    float acc[4][4][4];
#pragma unroll
    for (int j = 0; j < 4; j++)
#pragma unroll
        for (int jj = 0; jj < 4; jj++)
#pragma unroll
            for (int q = 0; q < 4; q++) acc[j][jj][q] = 0.0f;

    // staging coords: per thread 2 x 16B chunks per plane covering 128x32 bf16
    const int lr = tid >> 2;            // row 0..63 (+64 for t=1)
    const int lc = (tid & 3) * 16;      // byte col 0..48 within 64B row

    const uint32_t lrow = (uint32_t)(ln & 15);
    const uint32_t lk16 = (uint32_t)((ln >> 4) * 16);

    uint4 pa[2], pb[2], pal[2], pbl[2];
    auto loadAB = [&](int kc) {
#pragma unroll
        for (int t = 0; t < 2; t++) {
            const int r = lr + t * 64;
            const long soff = (long)r * K + kc + (lc >> 1);   // lc bytes -> elems
            pa[t] = *(const uint4*)(Ah + soff);
            pb[t] = *(const uint4*)(Bh + soff);
            if (TERMS == 3) {
                pal[t] = *(const uint4*)(Al + soff);
                pbl[t] = *(const uint4*)(Bl + soff);
            }
        }
    };

    loadAB(0);
    for (int kc = 0; kc < K; kc += 32) {
        __syncthreads();                 // previous chunk fully consumed
#pragma unroll
        for (int t = 0; t < 2; t++) {
            const uint32_t doff = (uint32_t)((lr + t * 64) * 80 + lc);
            *(uint4*)(sm + OFF_AH + doff) = pa[t];
            *(uint4*)(sm + OFF_BH + doff) = pb[t];
            if (TERMS == 3) {
                *(uint4*)(sm + OFF_AL + doff) = pal[t];
                *(uint4*)(sm + OFF_BL + doff) = pbl[t];
            }
        }
        __syncthreads();                 // chunk staged
        if (kc + 32 < K) loadAB(kc + 32);   // prefetch next chunk over MMA

#pragma unroll
        for (int h = 0; h < 2; h++) {    // two k16 halves
            uint32_t bh[8], bl[8];
#pragma unroll
            for (int t = 0; t < 2; t++) {
                const uint32_t ba = (uint32_t)(nb + t * 16 + lrow) * 80u
                                  + (uint32_t)h * 32u + lk16;
                ldsm4(&bh[t * 4], sb + OFF_BH + ba);
                if (TERMS == 3) ldsm4(&bl[t * 4], sb + OFF_BL + ba);
            }
#pragma unroll
            for (int j = 0; j < 4; j++) {
                uint32_t ah[4], al[4];
                const uint32_t aa = (uint32_t)(mb + j * 16 + lrow) * 80u
                                  + (uint32_t)h * 32u + lk16;
                ldsm4(ah, sb + OFF_AH + aa);
                if (TERMS == 3) ldsm4(al, sb + OFF_AL + aa);
#pragma unroll
                for (int jj = 0; jj < 4; jj++) {
                    const int t = jj >> 1, s = jj & 1;
                    uint32_t bhr[2] = { bh[t * 4 + s], bh[t * 4 + 2 + s] };
                    hmma(acc[j][jj], ah, bhr);               // hi*hi
                    if (TERMS == 3) {
                        uint32_t blr[2] = { bl[t * 4 + s], bl[t * 4 + 2 + s] };
                        hmma(acc[j][jj], ah, blr);           // hi*lo
                        hmma(acc[j][jj], al, bhr);           // lo*hi
                    }
                }
            }
        }
    }

    // ---- epilogue ----
    const int g = ln >> 2, tig = ln & 3;
#pragma unroll
    for (int j = 0; j < 4; j++) {
        const int mlo = m0 + mb + j * 16 + g;
        float rs0 = 1.0f, rs1 = 1.0f;
        if (OMODE == 2) {
            rs0 = rowscale[(long)z * M + mlo];
            rs1 = rowscale[(long)z * M + mlo + 8];
        }
#pragma unroll
        for (int jj = 0; jj < 4; jj++) {
            const int n = n0 + nb + jj * 8 + tig * 2;
            float b0 = 0.0f, b1 = 0.0f;
            if (bias) { b0 = bias[n]; b1 = bias[n + 1]; }
            float v0 = acc[j][jj][0], v1 = acc[j][jj][1];
            float v2 = acc[j][jj][2], v3 = acc[j][jj][3];
            if (DO_EXP) {
                v0 = __expf(v0 * alpha); v1 = __expf(v1 * alpha);
                v2 = __expf(v2 * alpha); v3 = __expf(v3 * alpha);
            }
            if (OMODE == 2) {
                float* C = (float*)O1 + (long)z * bsC;
                v0 = v0 * rs0 + b0; v1 = v1 * rs0 + b1;
                v2 = v2 * rs1 + b0; v3 = v3 * rs1 + b1;
                *(float2*)(C + (long)mlo * N + n)       = make_float2(v0, v1);
                *(float2*)(C + (long)(mlo + 8) * N + n) = make_float2(v2, v3);
            } else {
                v0 += b0; v1 += b1; v2 += b0; v3 += b1;
                __nv_bfloat16* Ch = (__nv_bfloat16*)O1 + (long)z * bsC;
                uint32_t h01 = pk2(v0, v1);
                uint32_t h23 = pk2(v2, v3);
                *(uint32_t*)(Ch + (long)mlo * N + n)       = h01;
                *(uint32_t*)(Ch + (long)(mlo + 8) * N + n) = h23;
                if (OMODE == 0) {
                    __nv_bfloat16* Cl = (__nv_bfloat16*)O2 + (long)z * bsC;
                    float f0 = __uint_as_float(h01 << 16);
                    float f1 = __uint_as_float(h01 & 0xffff0000u);
                    float f2 = __uint_as_float(h23 << 16);
                    float f3 = __uint_as_float(h23 & 0xffff0000u);
                    *(uint32_t*)(Cl + (long)mlo * N + n)       = pk2(v0 - f0, v1 - f1);
                    *(uint32_t*)(Cl + (long)(mlo + 8) * N + n) = pk2(v2 - f2, v3 - f3);
                }
            }
        }
    }
}

// ---------------------------------------------------------------------------
// Prep kernels
// ---------------------------------------------------------------------------
// Split fp32 array into bf16 hi/lo planes. count multiple of 1024.
__global__ void splitK(const float* __restrict__ src, __nv_bfloat16* __restrict__ h,
                       __nv_bfloat16* __restrict__ l)
{
    const long i = ((long)blockIdx.x * blockDim.x + threadIdx.x) * 4;
    float4 v = *(const float4*)(src + i);
    uint2 hh, ll;
    split4(v, hh, ll);
    *(uint2*)(h + i) = hh;
    *(uint2*)(l + i) = ll;
}

// dst[Cc][R] = split(src[R][Cc]^T). block (32,8), grid (Cc/32, R/32)
__global__ void transpose_split(const float* __restrict__ src,
                                __nv_bfloat16* __restrict__ dh,
                                __nv_bfloat16* __restrict__ dl, int R, int Cc)
{
    __shared__ float t[32][33];
    int bx = blockIdx.x * 32, by = blockIdx.y * 32;
#pragma unroll
    for (int i = 0; i < 32; i += 8)
        t[threadIdx.y + i][threadIdx.x] = src[(long)(by + threadIdx.y + i) * Cc + bx + threadIdx.x];
    __syncthreads();
#pragma unroll
    for (int i = 0; i < 32; i += 8) {
        float v = t[threadIdx.x][threadIdx.y + i];
        __nv_bfloat16 hb = __float2bfloat16(v);
        long o = (long)(bx + threadIdx.y + i) * R + by + threadIdx.x;
        dh[o] = hb;
        dl[o] = __float2bfloat16(v - __bfloat162float(hb));
    }
}

// bo2[d] = sum_m bv[m] * Wo[m,d] + bo[d]
__global__ void make_bo2(const float* __restrict__ bv, const float* __restrict__ Wo,
                         const float* __restrict__ bo, float* __restrict__ bo2)
{
    const int d = blockIdx.x * blockDim.x + threadIdx.x;   // 0..511
    float s = bo[d];
    for (int m = 0; m < DQ_; m++) s += bv[m] * Wo[m * DQ_ + d];
    bo2[d] = s;
}

// R[row] = 1 / sum_k (Eh[row,k] + El[row,k]). 8 rows per CTA, block (32,8)
__global__ void rowsum_recip(const __nv_bfloat16* __restrict__ Eh,
                             const __nv_bfloat16* __restrict__ El,
                             float* __restrict__ R, int ncols)
{
    const int row = blockIdx.x * 8 + threadIdx.y;
    const uint4* ph = (const uint4*)(Eh + (long)row * ncols);
    const uint4* pl = (const uint4*)(El + (long)row * ncols);
    float s = 0.0f;
    for (int i = threadIdx.x; i < (ncols >> 3); i += 32) {
        uint4 wh = ph[i], wl = pl[i];
        const uint32_t wsh[4] = {wh.x, wh.y, wh.z, wh.w};
        const uint32_t wsl[4] = {wl.x, wl.y, wl.z, wl.w};
#pragma unroll
        for (int q = 0; q < 4; q++) {
            float2 fh = __bfloat1622float2(*(const __nv_bfloat162*)&wsh[q]);
            float2 fl = __bfloat1622float2(*(const __nv_bfloat162*)&wsl[q]);
            s += (fh.x + fl.x) + (fh.y + fl.y);
        }
    }
#pragma unroll
    for (int o = 16; o > 0; o >>= 1) s += __shfl_xor_sync(0xffffffffu, s, o);
    if (threadIdx.x == 0) R[row] = 1.0f / s;
}

// ---------------------------------------------------------------------------
// kernel_launch
// ---------------------------------------------------------------------------
extern "C" void kernel_launch(void* const* d_in, const int* in_sizes, int n_in,
                              void* d_out, int out_size)
{
    (void)in_sizes; (void)n_in; (void)out_size;
    const float* query = (const float*)d_in[0];
    const float* key   = (const float*)d_in[1];
    const float* value = (const float*)d_in[2];
    const float* Wk    = (const float*)d_in[3];
    const float* bk    = (const float*)d_in[4];
    const float* Wv    = (const float*)d_in[5];
    const float* bv    = (const float*)d_in[6];
    const float* Wo    = (const float*)d_in[7];
    const float* bo    = (const float*)d_in[8];
    float* out = (float*)d_out;

    __nv_bfloat16 *Qh, *Ql, *keyh, *keyl, *valh, *vall, *Kph, *Kpl;
    __nv_bfloat16 *VpTh, *VpTl, *Eh, *El;
    __nv_bfloat16 *WkTh, *WkTl, *WoTh, *WoTl, *Wvh, *Wvl, *WvoTh, *WvoTl;
    float *R, *bo2;
    cudaGetSymbolAddress((void**)&Qh,   g_Qh);   cudaGetSymbolAddress((void**)&Ql,   g_Ql);
    cudaGetSymbolAddress((void**)&keyh, g_keyh); cudaGetSymbolAddress((void**)&keyl, g_keyl);
    cudaGetSymbolAddress((void**)&valh, g_valh); cudaGetSymbolAddress((void**)&vall, g_vall);
    cudaGetSymbolAddress((void**)&Kph,  g_Kph);  cudaGetSymbolAddress((void**)&Kpl,  g_Kpl);
    cudaGetSymbolAddress((void**)&VpTh, g_VpTh); cudaGetSymbolAddress((void**)&VpTl, g_VpTl);
    cudaGetSymbolAddress((void**)&Eh,   g_Eh);   cudaGetSymbolAddress((void**)&El,   g_El);
    cudaGetSymbolAddress((void**)&WkTh, g_WkTh); cudaGetSymbolAddress((void**)&WkTl, g_WkTl);
    cudaGetSymbolAddress((void**)&WoTh, g_WoTh); cudaGetSymbolAddress((void**)&WoTl, g_WoTl);
    cudaGetSymbolAddress((void**)&Wvh,  g_Wvh);  cudaGetSymbolAddress((void**)&Wvl,  g_Wvl);
    cudaGetSymbolAddress((void**)&WvoTh,g_WvoTh);cudaGetSymbolAddress((void**)&WvoTl,g_WvoTl);
    cudaGetSymbolAddress((void**)&R,    g_R);    cudaGetSymbolAddress((void**)&bo2,  g_bo2);

    // ---- prep: split inputs, transpose+split weights, folded bias ----
    splitK<<<(B_*LQ_*DQ_)/1024, 256>>>(query, Qh, Ql);
    splitK<<<(B_*LKV_*DC_)/1024, 256>>>(key,   keyh, keyl);
    splitK<<<(B_*LKV_*DC_)/1024, 256>>>(value, valh, vall);
    splitK<<<(DC_*DQ_)/1024, 256>>>(Wv, Wvh, Wvl);
    transpose_split<<<dim3(DQ_/32, DC_/32), dim3(32, 8)>>>(Wk, WkTh, WkTl, DC_, DQ_);
    transpose_split<<<dim3(DQ_/32, DQ_/32), dim3(32, 8)>>>(Wo, WoTh, WoTl, DQ_, DQ_);
    make_bo2<<<2, 256>>>(bv, Wo, bo, bo2);

    // G1) WvoT[d,c] = sum_e WoT[d,e]*Wv[c,e]      M=512 N=768 K=512  (pair out)
    bgemm<3,0,0><<<dim3(6, 4, 1), 256>>>(
        WoTh, WoTl, Wvh, Wvl, WvoTh, WvoTl,
        512, 768, 512, 0, 0, 0, nullptr, nullptr, 1.0f);

    // G2) Kp = key @ WkT^T + bk                   M=2048 N=512 K=768 (pair out)
    bgemm<3,0,0><<<dim3(4, 16, 8), 256>>>(
        keyh, keyl, WkTh, WkTl, Kph, Kpl,
        2048, 512, 768, (long)2048*768, 0, (long)2048*512, bk, nullptr, 1.0f);

    // G3) VpT = WvoT @ value^T                    M=512 N=2048 K=768 (pair out)
    bgemm<3,0,0><<<dim3(16, 4, 8), 256>>>(
        WvoTh, WvoTl, valh, vall, VpTh, VpTl,
        512, 2048, 768, 0, (long)2048*768, (long)512*2048, nullptr, nullptr, 1.0f);

    // G4) E = exp(scale * Q @ Kp^T)               M=2048 N=2048 K=512 (pair out)
    bgemm<3,1,0><<<dim3(16, 16, 8), 256>>>(
        Qh, Ql, Kph, Kpl, Eh, El,
        2048, 2048, 512, (long)2048*512, (long)2048*512, (long)2048*2048,
        nullptr, nullptr, ATT_SCALE);

    // G5 prep) R = 1 / rowsum(Eh + El)
    rowsum_recip<<<(B_ * LQ_) / 8, dim3(32, 8)>>>(Eh, El, R, LKV_);

    // G5) out = diag(R) * (E @ VpT^T) + bo2       M=2048 N=512 K=2048 (fp32 out)
    bgemm<3,0,2><<<dim3(4, 16, 8), 256>>>(
        Eh, El, VpTh, VpTl, out, nullptr,
        2048, 512, 2048, (long)2048*2048, (long)512*2048, (long)2048*512,
        bo2, R, 1.0f);
}

// round 16
// speedup vs baseline: 1.0252x; 1.0252x over previous
#include <cuda_runtime.h>
#include <cuda_bf16.h>
#include <cstdint>

// ---------------------------------------------------------------------------
// Problem constants
// ---------------------------------------------------------------------------
#define B_    8
#define LQ_   2048
#define LKV_  2048
#define DQ_   512
#define DC_   768
#define ATT_SCALE 0.044194173824159216f   // 1/sqrt(512)

// ---------------------------------------------------------------------------
// Scratch (device globals — runtime allocation is forbidden).
// ---------------------------------------------------------------------------
__device__ __align__(256) __nv_bfloat16 g_Qh  [(size_t)B_ * LQ_  * DQ_];
__device__ __align__(256) __nv_bfloat16 g_Ql  [(size_t)B_ * LQ_  * DQ_];
__device__ __align__(256) __nv_bfloat16 g_keyh[(size_t)B_ * LKV_ * DC_];
__device__ __align__(256) __nv_bfloat16 g_keyl[(size_t)B_ * LKV_ * DC_];
__device__ __align__(256) __nv_bfloat16 g_valh[(size_t)B_ * LKV_ * DC_];
__device__ __align__(256) __nv_bfloat16 g_vall[(size_t)B_ * LKV_ * DC_];
__device__ __align__(256) __nv_bfloat16 g_Kph [(size_t)B_ * LKV_ * DQ_];   // key@Wk+bk (pair)
__device__ __align__(256) __nv_bfloat16 g_Kpl [(size_t)B_ * LKV_ * DQ_];
__device__ __align__(256) __nv_bfloat16 g_VpTh[(size_t)B_ * DQ_ * LKV_];   // (value@Wvo)^T (pair)
__device__ __align__(256) __nv_bfloat16 g_VpTl[(size_t)B_ * DQ_ * LKV_];
__device__ __align__(256) float         g_E   [(size_t)B_ * LQ_ * LKV_];   // exp(scale*QKp^T) fp32
__device__ __align__(256) __nv_bfloat16 g_WkTh[(size_t)DQ_ * DC_];
__device__ __align__(256) __nv_bfloat16 g_WkTl[(size_t)DQ_ * DC_];
__device__ __align__(256) __nv_bfloat16 g_WoTh[(size_t)DQ_ * DQ_];
__device__ __align__(256) __nv_bfloat16 g_WoTl[(size_t)DQ_ * DQ_];
__device__ __align__(256) __nv_bfloat16 g_Wvh [(size_t)DC_ * DQ_];
__device__ __align__(256) __nv_bfloat16 g_Wvl [(size_t)DC_ * DQ_];
__device__ __align__(256) __nv_bfloat16 g_WvoTh[(size_t)DQ_ * DC_];        // (Wv@Wo)^T (pair)
__device__ __align__(256) __nv_bfloat16 g_WvoTl[(size_t)DQ_ * DC_];
__device__ __align__(256) float g_R  [(size_t)B_ * LQ_];                   // recip row sums
__device__ __align__(256) float g_bo2[DQ_];                                // bv@Wo + bo

// ---------------------------------------------------------------------------
// PTX helpers — baseline sm_103 ISA only (NO tcgen05, NO cp.async)
// ---------------------------------------------------------------------------
__device__ __forceinline__ uint32_t smem_u32(const void* p) {
    uint32_t a;
    asm("{ .reg .u64 t; cvta.to.shared.u64 t, %1; cvt.u32.u64 %0, t; }"
        : "=r"(a) : "l"(p));
    return a;
}
// ldmatrix x4: four 8x8 b16 tiles
__device__ __forceinline__ void ldsm4(uint32_t* r, uint32_t addr) {
    asm volatile("ldmatrix.sync.aligned.m8n8.x4.shared.b16 {%0,%1,%2,%3}, [%4];"
        : "=r"(r[0]), "=r"(r[1]), "=r"(r[2]), "=r"(r[3]) : "r"(addr));
}
// mma m16n8k16 bf16 -> f32 accumulate
__device__ __forceinline__ void hmma(float* d, const uint32_t* a, const uint32_t* b) {
    asm volatile(
        "mma.sync.aligned.m16n8k16.row.col.f32.bf16.bf16.f32 "
        "{%0,%1,%2,%3}, {%4,%5,%6,%7}, {%8,%9}, {%0,%1,%2,%3};"
        : "+f"(d[0]), "+f"(d[1]), "+f"(d[2]), "+f"(d[3])
        : "r"(a[0]), "r"(a[1]), "r"(a[2]), "r"(a[3]), "r"(b[0]), "r"(b[1]));
}
// Pack two fp32 into bf16x2. Result low half = first arg.
__device__ __forceinline__ uint32_t pk2(float lo, float hi) {
    uint32_t r;
    asm("cvt.rn.bf16x2.f32 %0, %1, %2;" : "=r"(r) : "f"(hi), "f"(lo));
    return r;
}
// Split float4 into bf16-hi quad + bf16-lo (residual) quad
__device__ __forceinline__ void split4(float4 v, uint2& h, uint2& l) {
    uint32_t h01 = pk2(v.x, v.y);
    uint32_t h23 = pk2(v.z, v.w);
    float f0 = __uint_as_float(h01 << 16);
    float f1 = __uint_as_float(h01 & 0xffff0000u);
    float f2 = __uint_as_float(h23 << 16);
    float f3 = __uint_as_float(h23 & 0xffff0000u);
    h = make_uint2(h01, h23);
    l = make_uint2(pk2(v.x - f0, v.y - f1), pk2(v.z - f2, v.w - f3));
}

// ---------------------------------------------------------------------------
// Tensor-core NT GEMM:
//   C[m,n] = epi( sum_k A[m,k]*B[n,k] )   A:[M,K]  B:[N,K]  k-contiguous
// TERMS==3: a=Ah+Al, b=Bh+Bl, 3 MMAs (ah*bh+ah*bl+al*bh) -> fp32-class
// TERMS==1: plain bf16, 1 MMA
// ASPLIT==1 (requires TERMS==3): A is a single fp32 plane (Ah cast), split
//   into hi/lo bf16 planes in registers during staging (R11-proven path).
// OMODE: 0 = bf16 hi+lo pair out; 1 = bf16 hi out;
//        2 = fp32 out, v = (opt exp(v*alpha)) * rowscale?[m] + bias?[n]
// CTA tile 128x128, k-chunk 32, single static smem buffer + register
// prefetch. 8 warps, 64x32 warp tiles. 80B smem pitch -> conflict-free ldsm.
// ---------------------------------------------------------------------------
template <int TERMS, int DO_EXP, int OMODE, int ASPLIT>
__global__ __launch_bounds__(256, 2)
void bgemm(const __nv_bfloat16* __restrict__ Ah, const __nv_bfloat16* __restrict__ Al,
           const __nv_bfloat16* __restrict__ Bh, const __nv_bfloat16* __restrict__ Bl,
           void* __restrict__ O1, void* __restrict__ O2,
           int M, int N, int K, long bsA, long bsB, long bsC,
           const float* __restrict__ bias, const float* __restrict__ rowscale,
           float alpha)
{
    constexpr int PLB    = 10240;                    // 128 rows * 80B pitch
    constexpr int OFF_AH = 0;
    constexpr int OFF_AL = PLB;                      // TERMS==3 only
    constexpr int OFF_BH = (TERMS == 3) ? 2 * PLB : PLB;
    constexpr int OFF_BL = 3 * PLB;                  // TERMS==3 only

    __shared__ __align__(128) char sm[(TERMS == 3) ? 4 * PLB : 2 * PLB];
    const uint32_t sb = smem_u32(sm);

    const int tid  = threadIdx.x;
    const int warp = tid >> 5, ln = tid & 31;
    const int z    = blockIdx.z;
    const int n0   = blockIdx.x * 128;
    const int m0   = blockIdx.y * 128;

    const float* Af = (const float*)Ah;              // ASPLIT view
    if (ASPLIT) Af += (long)z * bsA + (long)m0 * K;
    else        Ah += (long)z * bsA + (long)m0 * K;
    Bh += (long)z * bsB + (long)n0 * K;
    if (TERMS == 3) {
        if (!ASPLIT) Al += (long)z * bsA + (long)m0 * K;
        Bl += (long)z * bsB + (long)n0 * K;
    }

    const int mb = (warp >> 2) * 64;
    const int nb = (warp & 3) * 32;

    float acc[4][4][4];
#pragma unroll
    for (int j = 0; j < 4; j++)
#pragma unroll
        for (int jj = 0; jj < 4; jj++)
#pragma unroll
            for (int q = 0; q < 4; q++) acc[j][jj][q] = 0.0f;

    // bf16-plane staging coords: per thread 2 x 16B chunks per plane (128x32)
    const int lr = tid >> 2;            // row 0..63 (+64 for t=1)
    const int lc = (tid & 3) * 16;      // byte col 0..48 within 64B bf16 row
    // fp32-A staging coords: per thread 4 x 16B chunks (128 rows x 128B)
    const int fr = tid >> 3;            // row 0..31 (+32 per t)
    const int fc = (tid & 7) * 4;       // fp32 col 0,4,...,28

    const uint32_t lrow = (uint32_t)(ln & 15);
    const uint32_t lk16 = (uint32_t)((ln >> 4) * 16);

    uint4 pa[2], pb[2], pal[2], pbl[2];
    float4 fa[4];
    auto loadAB = [&](int kc) {
        if (ASPLIT) {
#pragma unroll
            for (int t = 0; t < 4; t++)
                fa[t] = *(const float4*)(Af + (long)(fr + t * 32) * K + kc + fc);
        } else {
#pragma unroll
            for (int t = 0; t < 2; t++) {
                const long soff = (long)(lr + t * 64) * K + kc + (lc >> 1);
                pa[t] = *(const uint4*)(Ah + soff);
                if (TERMS == 3) pal[t] = *(const uint4*)(Al + soff);
            }
        }
#pragma unroll
        for (int t = 0; t < 2; t++) {
            const long soff = (long)(lr + t * 64) * K + kc + (lc >> 1);
            pb[t] = *(const uint4*)(Bh + soff);
            if (TERMS == 3) pbl[t] = *(const uint4*)(Bl + soff);
        }
    };

    loadAB(0);
    for (int kc = 0; kc < K; kc += 32) {
        __syncthreads();                 // previous chunk fully consumed
        if (ASPLIT) {
#pragma unroll
            for (int t = 0; t < 4; t++) {
                const uint32_t doff = (uint32_t)((fr + t * 32) * 80 + fc * 2);
                uint2 h, l;
                split4(fa[t], h, l);
                *(uint2*)(sm + OFF_AH + doff) = h;
                *(uint2*)(sm + OFF_AL + doff) = l;
            }
        } else {
#pragma unroll
            for (int t = 0; t < 2; t++) {
                const uint32_t doff = (uint32_t)((lr + t * 64) * 80 + lc);
                *(uint4*)(sm + OFF_AH + doff) = pa[t];
                if (TERMS == 3) *(uint4*)(sm + OFF_AL + doff) = pal[t];
            }
        }
#pragma unroll
        for (int t = 0; t < 2; t++) {
            const uint32_t doff = (uint32_t)((lr + t * 64) * 80 + lc);
            *(uint4*)(sm + OFF_BH + doff) = pb[t];
            if (TERMS == 3) *(uint4*)(sm + OFF_BL + doff) = pbl[t];
        }
        __syncthreads();                 // chunk staged
        if (kc + 32 < K) loadAB(kc + 32);   // prefetch next chunk over MMA

#pragma unroll
        for (int h = 0; h < 2; h++) {    // two k16 halves
            uint32_t bh[8], bl[8];
#pragma unroll
            for (int t = 0; t < 2; t++) {
                const uint32_t ba = (uint32_t)(nb + t * 16 + lrow) * 80u
                                  + (uint32_t)h * 32u + lk16;
                ldsm4(&bh[t * 4], sb + OFF_BH + ba);
                if (TERMS == 3) ldsm4(&bl[t * 4], sb + OFF_BL + ba);
            }
#pragma unroll
            for (int j = 0; j < 4; j++) {
                uint32_t ah[4], al[4];
                const uint32_t aa = (uint32_t)(mb + j * 16 + lrow) * 80u
                                  + (uint32_t)h * 32u + lk16;
                ldsm4(ah, sb + OFF_AH + aa);
                if (TERMS == 3) ldsm4(al, sb + OFF_AL + aa);
#pragma unroll
                for (int jj = 0; jj < 4; jj++) {
                    const int t = jj >> 1, s = jj & 1;
                    uint32_t bhr[2] = { bh[t * 4 + s], bh[t * 4 + 2 + s] };
                    hmma(acc[j][jj], ah, bhr);               // hi*hi
                    if (TERMS == 3) {
                        uint32_t blr[2] = { bl[t * 4 + s], bl[t * 4 + 2 + s] };
                        hmma(acc[j][jj], ah, blr);           // hi*lo
                        hmma(acc[j][jj], al, bhr);           // lo*hi
                    }
                }
            }
        }
    }

    // ---- epilogue ----
    const int g = ln >> 2, tig = ln & 3;
#pragma unroll
    for (int j = 0; j < 4; j++) {
        const int mlo = m0 + mb + j * 16 + g;
        float rs0 = 1.0f, rs1 = 1.0f;
        if (OMODE == 2 && rowscale) {
            rs0 = rowscale[(long)z * M + mlo];
            rs1 = rowscale[(long)z * M + mlo + 8];
        }
#pragma unroll
        for (int jj = 0; jj < 4; jj++) {
            const int n = n0 + nb + jj * 8 + tig * 2;
            float b0 = 0.0f, b1 = 0.0f;
            if (bias) { b0 = bias[n]; b1 = bias[n + 1]; }
            float v0 = acc[j][jj][0], v1 = acc[j][jj][1];
            float v2 = acc[j][jj][2], v3 = acc[j][jj][3];
            if (DO_EXP) {
                v0 = __expf(v0 * alpha); v1 = __expf(v1 * alpha);
                v2 = __expf(v2 * alpha); v3 = __expf(v3 * alpha);
            }
            if (OMODE == 2) {
                float* C = (float*)O1 + (long)z * bsC;
                v0 = v0 * rs0 + b0; v1 = v1 * rs0 + b1;
                v2 = v2 * rs1 + b0; v3 = v3 * rs1 + b1;
                *(float2*)(C + (long)mlo * N + n)       = make_float2(v0, v1);
                *(float2*)(C + (long)(mlo + 8) * N + n) = make_float2(v2, v3);
            } else {
                v0 += b0; v1 += b1; v2 += b0; v3 += b1;
                __nv_bfloat16* Ch = (__nv_bfloat16*)O1 + (long)z * bsC;
                uint32_t h01 = pk2(v0, v1);
                uint32_t h23 = pk2(v2, v3);
                *(uint32_t*)(Ch + (long)mlo * N + n)       = h01;
                *(uint32_t*)(Ch + (long)(mlo + 8) * N + n) = h23;
                if (OMODE == 0) {
                    __nv_bfloat16* Cl = (__nv_bfloat16*)O2 + (long)z * bsC;
                    float f0 = __uint_as_float(h01 << 16);
                    float f1 = __uint_as_float(h01 & 0xffff0000u);
                    float f2 = __uint_as_float(h23 << 16);
                    float f3 = __uint_as_float(h23 & 0xffff0000u);
                    *(uint32_t*)(Cl + (long)mlo * N + n)       = pk2(v0 - f0, v1 - f1);
                    *(uint32_t*)(Cl + (long)(mlo + 8) * N + n) = pk2(v2 - f2, v3 - f3);
                }
            }
        }
    }
}

// ---------------------------------------------------------------------------
// Prep kernels
// ---------------------------------------------------------------------------
// Split fp32 array into bf16 hi/lo planes. count multiple of 1024.
__global__ void splitK(const float* __restrict__ src, __nv_bfloat16* __restrict__ h,
                       __nv_bfloat16* __restrict__ l)
{
    const long i = ((long)blockIdx.x * blockDim.x + threadIdx.x) * 4;
    float4 v = *(const float4*)(src + i);
    uint2 hh, ll;
    split4(v, hh, ll);
    *(uint2*)(h + i) = hh;
    *(uint2*)(l + i) = ll;
}

// dst[Cc][R] = split(src[R][Cc]^T). block (32,8), grid (Cc/32, R/32)
__global__ void transpose_split(const float* __restrict__ src,
                                __nv_bfloat16* __restrict__ dh,
                                __nv_bfloat16* __restrict__ dl, int R, int Cc)
{
    __shared__ float t[32][33];
    int bx = blockIdx.x * 32, by = blockIdx.y * 32;
#pragma unroll
    for (int i = 0; i < 32; i += 8)
        t[threadIdx.y + i][threadIdx.x] = src[(long)(by + threadIdx.y + i) * Cc + bx + threadIdx.x];
    __syncthreads();
#pragma unroll
    for (int i = 0; i < 32; i += 8) {
        float v = t[threadIdx.x][threadIdx.y + i];
        __nv_bfloat16 hb = __float2bfloat16(v);
        long o = (long)(bx + threadIdx.y + i) * R + by + threadIdx.x;
        dh[o] = hb;
        dl[o] = __float2bfloat16(v - __bfloat162float(hb));
    }
}

// bo2[d] = sum_m bv[m] * Wo[m,d] + bo[d]
__global__ void make_bo2(const float* __restrict__ bv, const float* __restrict__ Wo,
                         const float* __restrict__ bo, float* __restrict__ bo2)
{
    const int d = blockIdx.x * blockDim.x + threadIdx.x;   // 0..511
    float s = bo[d];
    for (int m = 0; m < DQ_; m++) s += bv[m] * Wo[m * DQ_ + d];
    bo2[d] = s;
}

// R[row] = 1 / sum_k E[row,k] (fp32). 8 rows per CTA, block (32,8)
__global__ void rowsum_recip(const float* __restrict__ E, float* __restrict__ R,
                             int ncols)
{
    const int row = blockIdx.x * 8 + threadIdx.y;
    const float4* p = (const float4*)(E + (long)row * ncols);
    float s = 0.0f;
    for (int i = threadIdx.x; i < (ncols >> 2); i += 32) {
        float4 v = p[i];
        s += (v.x + v.y) + (v.z + v.w);
    }
#pragma unroll
    for (int o = 16; o > 0; o >>= 1) s += __shfl_xor_sync(0xffffffffu, s, o);
    if (threadIdx.x == 0) R[row] = 1.0f / s;
}

// ---------------------------------------------------------------------------
// kernel_launch
// ---------------------------------------------------------------------------
extern "C" void kernel_launch(void* const* d_in, const int* in_sizes, int n_in,
                              void* d_out, int out_size)
{
    (void)in_sizes; (void)n_in; (void)out_size;
    const float* query = (const float*)d_in[0];
    const float* key   = (const float*)d_in[1];
    const float* value = (const float*)d_in[2];
    const float* Wk    = (const float*)d_in[3];
    const float* bk    = (const float*)d_in[4];
    const float* Wv    = (const float*)d_in[5];
    const float* bv    = (const float*)d_in[6];
    const float* Wo    = (const float*)d_in[7];
    const float* bo    = (const float*)d_in[8];
    float* out = (float*)d_out;

    __nv_bfloat16 *Qh, *Ql, *keyh, *keyl, *valh, *vall, *Kph, *Kpl, *VpTh, *VpTl;
    __nv_bfloat16 *WkTh, *WkTl, *WoTh, *WoTl, *Wvh, *Wvl, *WvoTh, *WvoTl;
    float *E, *R, *bo2;
    cudaGetSymbolAddress((void**)&Qh,   g_Qh);   cudaGetSymbolAddress((void**)&Ql,   g_Ql);
    cudaGetSymbolAddress((void**)&keyh, g_keyh); cudaGetSymbolAddress((void**)&keyl, g_keyl);
    cudaGetSymbolAddress((void**)&valh, g_valh); cudaGetSymbolAddress((void**)&vall, g_vall);
    cudaGetSymbolAddress((void**)&Kph,  g_Kph);  cudaGetSymbolAddress((void**)&Kpl,  g_Kpl);
    cudaGetSymbolAddress((void**)&VpTh, g_VpTh); cudaGetSymbolAddress((void**)&VpTl, g_VpTl);
    cudaGetSymbolAddress((void**)&E,    g_E);
    cudaGetSymbolAddress((void**)&WkTh, g_WkTh); cudaGetSymbolAddress((void**)&WkTl, g_WkTl);
    cudaGetSymbolAddress((void**)&WoTh, g_WoTh); cudaGetSymbolAddress((void**)&WoTl, g_WoTl);
    cudaGetSymbolAddress((void**)&Wvh,  g_Wvh);  cudaGetSymbolAddress((void**)&Wvl,  g_Wvl);
    cudaGetSymbolAddress((void**)&WvoTh,g_WvoTh);cudaGetSymbolAddress((void**)&WvoTl,g_WvoTl);
    cudaGetSymbolAddress((void**)&R,    g_R);    cudaGetSymbolAddress((void**)&bo2,  g_bo2);

    // ---- prep: split inputs, transpose+split weights, folded bias ----
    splitK<<<(B_*LQ_*DQ_)/1024, 256>>>(query, Qh, Ql);
    splitK<<<(B_*LKV_*DC_)/1024, 256>>>(key,   keyh, keyl);
    splitK<<<(B_*LKV_*DC_)/1024, 256>>>(value, valh, vall);
    splitK<<<(DC_*DQ_)/1024, 256>>>(Wv, Wvh, Wvl);
    transpose_split<<<dim3(DQ_/32, DC_/32), dim3(32, 8)>>>(Wk, WkTh, WkTl, DC_, DQ_);
    transpose_split<<<dim3(DQ_/32, DQ_/32), dim3(32, 8)>>>(Wo, WoTh, WoTl, DQ_, DQ_);
    make_bo2<<<2, 256>>>(bv, Wo, bo, bo2);

    // G1) WvoT[d,c] = sum_e WoT[d,e]*Wv[c,e]      M=512 N=768 K=512  (pair out)
    bgemm<3,0,0,0><<<dim3(6, 4, 1), 256>>>(
        WoTh, WoTl, Wvh, Wvl, WvoTh, WvoTl,
        512, 768, 512, 0, 0, 0, nullptr, nullptr, 1.0f);

    // G2) Kp = key @ WkT^T + bk                   M=2048 N=512 K=768 (pair out)
    bgemm<3,0,0,0><<<dim3(4, 16, 8), 256>>>(
        keyh, keyl, WkTh, WkTl, Kph, Kpl,
        2048, 512, 768, (long)2048*768, 0, (long)2048*512, bk, nullptr, 1.0f);

    // G3) VpT = WvoT @ value^T                    M=512 N=2048 K=768 (pair out)
    bgemm<3,0,0,0><<<dim3(16, 4, 8), 256>>>(
        WvoTh, WvoTl, valh, vall, VpTh, VpTl,
        512, 2048, 768, 0, (long)2048*768, (long)512*2048, nullptr, nullptr, 1.0f);

    // G4) E = exp(scale * Q @ Kp^T)               M=2048 N=2048 K=512 (fp32 out)
    bgemm<3,1,2,0><<<dim3(16, 16, 8), 256>>>(
        Qh, Ql, Kph, Kpl, E, nullptr,
        2048, 2048, 512, (long)2048*512, (long)2048*512, (long)2048*2048,
        nullptr, nullptr, ATT_SCALE);

    // G5 prep) R = 1 / rowsum(E)
    rowsum_recip<<<(B_ * LQ_) / 8, dim3(32, 8)>>>(E, R, LKV_);

    // G5) out = diag(R) * (E @ VpT^T) + bo2       M=2048 N=512 K=2048 (fp32 out)
    //     A = fp32 E, split in-kernel (ASPLIT); B = VpT pair planes.
    bgemm<3,0,2,1><<<dim3(4, 16, 8), 256>>>(
        (const __nv_bfloat16*)E, nullptr, VpTh, VpTl, out, nullptr,
        2048, 512, 2048, (long)2048*2048, (long)512*2048, (long)2048*512,
        bo2, R, 1.0f);
}